// round 14
// baseline (speedup 1.0000x reference)
#include <cuda_runtime.h>
#include <math.h>

// Problem dims
#define TT   512
#define BB   64
#define HH   300
#define KKT  9
#define G4   1200           // 4*H
#define NCOL 32768          // T*B columns (t*64+b)
#define HB   (HH*BB)        // 19200
#define NSL  75             // slices per direction (4 cols each); grid = 150
#define HROW 68             // padded h/x smem row stride (floats); quads at {0,16,36,52}
#define PROW 68             // part row stride (floats)

// rec smem layout (float offsets)
#define SM_H    0            // [304][HROW]         20672 floats
#define SM_PART 20672        // [256][PROW]         17408 floats
#define SM_PRE  38080        // 3 slots x [16][68]   3264 floats
#define SM_WIH  41344        // 16*306 ull           9792 floats
#define SM_TOTF 51136        // total floats (204544 B)

typedef unsigned long long ull;

// ---------------- scratch (device globals; no runtime allocation) ----------------
__device__ __align__(16) float g_xT[(size_t)HH * NCOL];
__device__ __align__(16) float g_h[(size_t)2 * (TT + 1) * HB];   // [dir][t+1][k][b]
__device__ float g_emis[(size_t)TT * BB * KKT];
__device__ float g_bias[2 * G4];
__device__ float g_lossb[BB];
__device__ unsigned int g_bar2[64];                // [0]=fwd ctr, [32]=bwd ctr

// ---------------- helpers ----------------
__device__ __forceinline__ ull dup2(float v) {
    ull r; asm("mov.b64 %0, {%1, %1};" : "=l"(r) : "f"(v)); return r;
}
__device__ __forceinline__ ull fma2(ull a, ull b, ull c) {
    ull d; asm("fma.rn.f32x2 %0, %1, %2, %3;" : "=l"(d) : "l"(a), "l"(b), "l"(c)); return d;
}
__device__ __forceinline__ float2 u2f(ull v) {
    float2 r; asm("mov.b64 {%0, %1}, %2;" : "=f"(r.x), "=f"(r.y) : "l"(v)); return r;
}
__device__ __forceinline__ float sig_(float x) { return 1.0f / (1.0f + __expf(-x)); }
__device__ __forceinline__ float tanh_(float x) {
    float e = __expf(-2.0f * fabsf(x));
    float r = (1.0f - e) / (1.0f + e);
    return copysignf(r, x);
}
__device__ __forceinline__ unsigned int smem_u32(const void* p) {
    unsigned int a;
    asm("{ .reg .u64 t; cvta.to.shared.u64 t, %1; cvt.u32.u64 %0, t; }" : "=r"(a) : "l"(p));
    return a;
}
__device__ __forceinline__ void cpa16(unsigned int dst, const void* src) {
    asm volatile("cp.async.cg.shared.global [%0], [%1], 16;" :: "r"(dst), "l"(src) : "memory");
}

// ---------------- K0: prep ----------------
__global__ void prep_kernel(const float* __restrict__ b_ih_f, const float* __restrict__ b_hh_f,
                            const float* __restrict__ b_ih_b, const float* __restrict__ b_hh_b,
                            const float* __restrict__ h0)
{
    int idx = blockIdx.x * blockDim.x + threadIdx.x;
    if (idx < 64) g_bar2[idx] = 0u;
    if (idx < 2 * G4) {
        g_bias[idx] = (idx < G4) ? (b_ih_f[idx] + b_hh_f[idx])
                                 : (b_ih_b[idx - G4] + b_hh_b[idx - G4]);
    }
    if (idx < 2 * HB) {
        int dir = idx / HB;
        int rem = idx - dir * HB;
        int k = rem >> 6;
        int b = rem & 63;
        g_h[(size_t)dir * (TT + 1) * HB + (size_t)k * BB + b] = h0[(size_t)(dir * BB + b) * HH + k];
    }
}

// ---------------- K1: embedding gather (smem transpose; both sides coalesced) ----------------
__global__ void gather_kernel(const int* __restrict__ tokens, const float* __restrict__ emb)
{
    extern __shared__ float xs[];              // [64][305]
    __shared__ int tok[BB];
    const int t = blockIdx.x;
    const int tid = threadIdx.x;               // 256
    if (tid < BB) tok[tid] = tokens[tid * TT + t];
    __syncthreads();

    const int w = tid >> 5, lane = tid & 31;
#pragma unroll
    for (int i = 0; i < 8; i++) {
        int b = w * 8 + i;
        const float* er = emb + (size_t)tok[b] * HH;
        for (int d = lane; d < HH; d += 32) xs[b * 305 + d] = er[d];
    }
    __syncthreads();

    const int b = tid & 63;
    const int dbase = tid >> 6;                // 0..3
    float* dst = g_xT + (size_t)t * BB + b;
    for (int d = dbase; d < HH; d += 4)
        dst[(size_t)d * NCOL] = xs[b * 305 + d];
}

// ---------------- K3: persistent fused LSTM (recurrence + input projection) ----------------
// grid = 150 (2 dir x 75 slices of 4 cols), 512 threads (16 warps).
// Per step: stage h(t) -> W_hh dot -> [issue x(t+2) stage into same buffer]
// -> finalize gates using smem pre-ring -> W_ih dot on x(t+2) (acc regs reused)
// -> reduce -> pre(t+2) into ring. The standalone input GEMM is eliminated;
// its FLOPs ride the recurrence's idle issue slots. pre pipeline is CTA-local.
__global__ void __launch_bounds__(512, 1) lstm_rec_kernel(const float* __restrict__ whh_f,
                                                          const float* __restrict__ whh_b,
                                                          const float* __restrict__ wih_f,
                                                          const float* __restrict__ wih_b,
                                                          const float* __restrict__ c0)
{
    extern __shared__ __align__(16) float sm_f[];
    float* h_sm     = sm_f + SM_H;
    float* part     = sm_f + SM_PART;
    float* pre_ring = sm_f + SM_PRE;           // 3 x [16][68]
    ull*   Wih2u    = (ull*)(sm_f + SM_WIH);   // [16 cg][306 k] dup'd

    const int bid = blockIdx.x;
    const int dir = bid & 1;
    const int s   = bid >> 1;                  // 0..74
    const int colbase = s * 4;

    const int tid  = threadIdx.x;
    const int ks   = tid >> 5;                 // 0..15 (19 k each)
    const int lane = tid & 31;
    const int bq   = lane >> 3;                // 0..3 batch quad (16 each)
    const int cgrp = lane & 7;                 // owns cg = cgrp, cgrp+8
    const int bqf  = (bq < 2) ? bq * 16 : 36 + (bq - 2) * 16;  // {0,16,36,52}

    const float* whh = dir ? whh_b : whh_f;
    const float* wih = dir ? wih_b : wih_f;

    // zero pad rows 300..303 (read by ks=15 in both dots; never staged; W=0 there)
    if (tid < 4 * HROW) h_sm[300 * HROW + tid] = 0.f;

    // W_hh -> registers
    const int cgA = cgrp,      cA = cgA >> 2, gA = cgA & 3;
    const int cgB = cgrp + 8,  cB = cgB >> 2, gB = cgB & 3;
    float WfA[19], WfB[19];
#pragma unroll
    for (int kk = 0; kk < 19; kk++) {
        int k = ks * 19 + kk;
        WfA[kk] = (k < 300) ? whh[(size_t)(gA * HH + colbase + cA) * HH + k] : 0.f;
        WfB[kk] = (k < 300) ? whh[(size_t)(gB * HH + colbase + cB) * HH + k] : 0.f;
    }

    // W_ih -> smem (duplicated pairs; 306-ull row stride -> conflict-free LDS.64)
    for (int idx = tid; idx < 16 * 304; idx += 512) {
        int cg = idx / 304, k = idx - cg * 304;
        int c = cg >> 2, g = cg & 3;
        float v = (k < 300) ? wih[(size_t)(g * HH + colbase + c) * HH + k] : 0.f;
        Wih2u[cg * 306 + k] = dup2(v);
    }

    // finalize role (first 256 threads): 1 column per thread
    const int ffc = (tid >> 6) & 3;
    const int ffb = tid & 63;
    const int fcol = (ffb < 32) ? ffb : ffb + 4;
    float cst = 0.f, bb0 = 0.f, bb1 = 0.f, bb2 = 0.f, bb3 = 0.f;
    if (tid < 256) {
        cst = c0[(size_t)(dir * BB + ffb) * HH + colbase + ffc];
        bb0 = g_bias[dir * G4 + 0 * HH + colbase + ffc];
        bb1 = g_bias[dir * G4 + 1 * HH + colbase + ffc];
        bb2 = g_bias[dir * G4 + 2 * HH + colbase + ffc];
        bb3 = g_bias[dir * G4 + 3 * HH + colbase + ffc];
    }

    __syncthreads();

    float*       ghdir = g_h + (size_t)dir * (TT + 1) * HB;
    unsigned int* ctr  = &g_bar2[dir * 32];

    const unsigned int hdst0 = smem_u32(h_sm + (size_t)ks * 19 * HROW);
    const float* hbase = h_sm + (size_t)ks * 19 * HROW + bqf;
    float* ppA = part + (size_t)(ks * 16 + cgA) * PROW + bqf;
    float* ppB = part + (size_t)(ks * 16 + cgB) * PROW + bqf;
    const ull* WiA = Wih2u + cgA * 306 + ks * 19;
    const ull* WiB = Wih2u + cgB * 306 + ks * 19;

    // ======== prologue: compute pre(0), pre(1) into ring slots 0,1 ========
    for (int pi = 0; pi < 2; pi++) {
        const int xcol = dir ? (TT - 1 - pi) : pi;
        const float* xbase = g_xT + (size_t)xcol * BB;
        // stage x(xcol) (warp-local)
        {
            const int nrows = (ks < 15) ? 19 : 15;
            for (int i = lane; i < nrows * 16; i += 32) {
                unsigned int dst = hdst0 + (i >> 4) * (HROW * 4) + (i & 15) * 16 + ((i & 8) << 1);
                cpa16(dst, (const float4*)(xbase + (size_t)(ks * 19 + (i >> 4)) * NCOL) + (i & 15));
            }
        }
        asm volatile("cp.async.commit_group;" ::: "memory");
        asm volatile("cp.async.wait_group 0;" ::: "memory");
        __syncwarp();
        // W_ih dot
        ull accA[8], accB[8];
#pragma unroll
        for (int i = 0; i < 8; i++) { accA[i] = 0ull; accB[i] = 0ull; }
#pragma unroll
        for (int kk = 0; kk < 19; kk++) {
            const ulonglong2* hp = (const ulonglong2*)(hbase + kk * HROW);
            ulonglong2 q0 = hp[0], q1 = hp[1], q2 = hp[2], q3 = hp[3];
            ull wA = WiA[kk], wB = WiB[kk];
            accA[0] = fma2(wA, q0.x, accA[0]); accA[1] = fma2(wA, q0.y, accA[1]);
            accA[2] = fma2(wA, q1.x, accA[2]); accA[3] = fma2(wA, q1.y, accA[3]);
            accA[4] = fma2(wA, q2.x, accA[4]); accA[5] = fma2(wA, q2.y, accA[5]);
            accA[6] = fma2(wA, q3.x, accA[6]); accA[7] = fma2(wA, q3.y, accA[7]);
            accB[0] = fma2(wB, q0.x, accB[0]); accB[1] = fma2(wB, q0.y, accB[1]);
            accB[2] = fma2(wB, q1.x, accB[2]); accB[3] = fma2(wB, q1.y, accB[3]);
            accB[4] = fma2(wB, q2.x, accB[4]); accB[5] = fma2(wB, q2.y, accB[5]);
            accB[6] = fma2(wB, q3.x, accB[6]); accB[7] = fma2(wB, q3.y, accB[7]);
        }
#pragma unroll
        for (int j = 0; j < 4; j++) {
            ulonglong2 v; v.x = accA[2 * j]; v.y = accA[2 * j + 1];
            *(ulonglong2*)(ppA + j * 4) = v;
        }
#pragma unroll
        for (int j = 0; j < 4; j++) {
            ulonglong2 v; v.x = accB[2 * j]; v.y = accB[2 * j + 1];
            *(ulonglong2*)(ppB + j * 4) = v;
        }
        __syncthreads();
        if (tid < 256) {
            float gv0 = bb0, gv1 = bb1, gv2 = bb2, gv3 = bb3;
#pragma unroll
            for (int kss = 0; kss < 16; kss++) {
                const float* pr = part + (size_t)(kss * 16 + ffc * 4) * PROW + fcol;
                gv0 += pr[0];
                gv1 += pr[PROW];
                gv2 += pr[2 * PROW];
                gv3 += pr[3 * PROW];
            }
            float* preD = pre_ring + pi * (16 * 68);
            preD[(0 + ffc) * 68 + ffb]  = gv0;
            preD[(4 + ffc) * 68 + ffb]  = gv1;
            preD[(8 + ffc) * 68 + ffb]  = gv2;
            preD[(12 + ffc) * 68 + ffb] = gv3;
        }
        __syncthreads();
    }

    // ======== main loop ========
    unsigned int target = 0;
    for (int t = 0; t < TT; t++) {
        // phase 1: stage h(t) (warp-local)
        const float4* hsrc = (const float4*)(ghdir + (size_t)t * HB) + ks * 19 * 16;
        if (ks < 15) {
#pragma unroll
            for (int j = 0; j < 9; j++) {
                int i = lane + 32 * j;
                unsigned int dst = hdst0 + (i >> 4) * (HROW * 4) + (i & 15) * 16 + ((i & 8) << 1);
                cpa16(dst, hsrc + i);
            }
            if (lane < 16) {
                int i = lane + 288;
                unsigned int dst = hdst0 + (i >> 4) * (HROW * 4) + (i & 15) * 16 + ((i & 8) << 1);
                cpa16(dst, hsrc + i);
            }
        } else {
#pragma unroll
            for (int j = 0; j < 7; j++) {
                int i = lane + 32 * j;
                unsigned int dst = hdst0 + (i >> 4) * (HROW * 4) + (i & 15) * 16 + ((i & 8) << 1);
                cpa16(dst, hsrc + i);
            }
            if (lane < 16) {
                int i = lane + 224;
                unsigned int dst = hdst0 + (i >> 4) * (HROW * 4) + (i & 15) * 16 + ((i & 8) << 1);
                cpa16(dst, hsrc + i);
            }
        }
        asm volatile("cp.async.commit_group;" ::: "memory");
        asm volatile("cp.async.wait_group 0;" ::: "memory");
        __syncwarp();

        // phase 2: W_hh dot
        ull accA[8], accB[8];
#pragma unroll
        for (int i = 0; i < 8; i++) { accA[i] = 0ull; accB[i] = 0ull; }
#pragma unroll
        for (int kk = 0; kk < 19; kk++) {
            const ulonglong2* hp = (const ulonglong2*)(hbase + kk * HROW);
            ulonglong2 q0 = hp[0], q1 = hp[1], q2 = hp[2], q3 = hp[3];
            ull wA = dup2(WfA[kk]);
            ull wB = dup2(WfB[kk]);
            accA[0] = fma2(wA, q0.x, accA[0]); accA[1] = fma2(wA, q0.y, accA[1]);
            accA[2] = fma2(wA, q1.x, accA[2]); accA[3] = fma2(wA, q1.y, accA[3]);
            accA[4] = fma2(wA, q2.x, accA[4]); accA[5] = fma2(wA, q2.y, accA[5]);
            accA[6] = fma2(wA, q3.x, accA[6]); accA[7] = fma2(wA, q3.y, accA[7]);
            accB[0] = fma2(wB, q0.x, accB[0]); accB[1] = fma2(wB, q0.y, accB[1]);
            accB[2] = fma2(wB, q1.x, accB[2]); accB[3] = fma2(wB, q1.y, accB[3]);
            accB[4] = fma2(wB, q2.x, accB[4]); accB[5] = fma2(wB, q2.y, accB[5]);
            accB[6] = fma2(wB, q3.x, accB[6]); accB[7] = fma2(wB, q3.y, accB[7]);
        }

        // phase 3: store h partials
#pragma unroll
        for (int j = 0; j < 4; j++) {
            ulonglong2 v; v.x = accA[2 * j]; v.y = accA[2 * j + 1];
            *(ulonglong2*)(ppA + j * 4) = v;
        }
#pragma unroll
        for (int j = 0; j < 4; j++) {
            ulonglong2 v; v.x = accB[2 * j]; v.y = accB[2 * j + 1];
            *(ulonglong2*)(ppB + j * 4) = v;
        }

        // phase 4: issue x(t+2) staging into own rows (overlaps finalize)
        const bool dog = (t + 2 < TT);
        if (dog) {
            const int xcol = dir ? (TT - 3 - t) : (t + 2);
            const float* xbase = g_xT + (size_t)xcol * BB;
            const int nrows = (ks < 15) ? 19 : 15;
            for (int i = lane; i < nrows * 16; i += 32) {
                unsigned int dst = hdst0 + (i >> 4) * (HROW * 4) + (i & 15) * 16 + ((i & 8) << 1);
                cpa16(dst, (const float4*)(xbase + (size_t)(ks * 19 + (i >> 4)) * NCOL) + (i & 15));
            }
            asm volatile("cp.async.commit_group;" ::: "memory");
        }
        __syncthreads();

        // phase 5: finalize gates (pre from smem ring)
        if (tid < 256) {
            const float* preS = pre_ring + (t % 3) * (16 * 68);
            float gv0 = preS[(0 + ffc) * 68 + ffb];
            float gv1 = preS[(4 + ffc) * 68 + ffb];
            float gv2 = preS[(8 + ffc) * 68 + ffb];
            float gv3 = preS[(12 + ffc) * 68 + ffb];
#pragma unroll
            for (int kss = 0; kss < 16; kss++) {
                const float* pr = part + (size_t)(kss * 16 + ffc * 4) * PROW + fcol;
                gv0 += pr[0];
                gv1 += pr[PROW];
                gv2 += pr[2 * PROW];
                gv3 += pr[3 * PROW];
            }
            float ig = sig_(gv0), fg = sig_(gv1), gt = tanh_(gv2), og = sig_(gv3);
            cst = fg * cst + ig * gt;
            ghdir[(size_t)(t + 1) * HB + (size_t)(colbase + ffc) * BB + ffb] = og * tanh_(cst);
        }

        // phase 6: W_ih dot on x(t+2) (acc registers reused)
        if (dog) {
            asm volatile("cp.async.wait_group 0;" ::: "memory");
            __syncwarp();
#pragma unroll
            for (int i = 0; i < 8; i++) { accA[i] = 0ull; accB[i] = 0ull; }
#pragma unroll
            for (int kk = 0; kk < 19; kk++) {
                const ulonglong2* hp = (const ulonglong2*)(hbase + kk * HROW);
                ulonglong2 q0 = hp[0], q1 = hp[1], q2 = hp[2], q3 = hp[3];
                ull wA = WiA[kk], wB = WiB[kk];
                accA[0] = fma2(wA, q0.x, accA[0]); accA[1] = fma2(wA, q0.y, accA[1]);
                accA[2] = fma2(wA, q1.x, accA[2]); accA[3] = fma2(wA, q1.y, accA[3]);
                accA[4] = fma2(wA, q2.x, accA[4]); accA[5] = fma2(wA, q2.y, accA[5]);
                accA[6] = fma2(wA, q3.x, accA[6]); accA[7] = fma2(wA, q3.y, accA[7]);
                accB[0] = fma2(wB, q0.x, accB[0]); accB[1] = fma2(wB, q0.y, accB[1]);
                accB[2] = fma2(wB, q1.x, accB[2]); accB[3] = fma2(wB, q1.y, accB[3]);
                accB[4] = fma2(wB, q2.x, accB[4]); accB[5] = fma2(wB, q2.y, accB[5]);
                accB[6] = fma2(wB, q3.x, accB[6]); accB[7] = fma2(wB, q3.y, accB[7]);
            }
        }
        __syncthreads();   // finalize part-reads done before overwrite

        // phase 7: store gemm partials
        if (dog) {
#pragma unroll
            for (int j = 0; j < 4; j++) {
                ulonglong2 v; v.x = accA[2 * j]; v.y = accA[2 * j + 1];
                *(ulonglong2*)(ppA + j * 4) = v;
            }
#pragma unroll
            for (int j = 0; j < 4; j++) {
                ulonglong2 v; v.x = accB[2 * j]; v.y = accB[2 * j + 1];
                *(ulonglong2*)(ppB + j * 4) = v;
            }
        }
        __syncthreads();

        // phase 8: reduce gemm partials + bias -> pre ring slot (t+2)%3
        if (dog && tid < 256) {
            float gv0 = bb0, gv1 = bb1, gv2 = bb2, gv3 = bb3;
#pragma unroll
            for (int kss = 0; kss < 16; kss++) {
                const float* pr = part + (size_t)(kss * 16 + ffc * 4) * PROW + fcol;
                gv0 += pr[0];
                gv1 += pr[PROW];
                gv2 += pr[2 * PROW];
                gv3 += pr[3 * PROW];
            }
            float* preD = pre_ring + ((t + 2) % 3) * (16 * 68);
            preD[(0 + ffc) * 68 + ffb]  = gv0;
            preD[(4 + ffc) * 68 + ffb]  = gv1;
            preD[(8 + ffc) * 68 + ffb]  = gv2;
            preD[(12 + ffc) * 68 + ffb] = gv3;
        }

        if (t == TT - 1) break;    // kernel boundary is the final sync

        // per-direction grid barrier (single counter; release-arrive + acquire-poll)
        target += NSL;
        __syncthreads();
        if (tid == 0) {
            asm volatile("red.release.gpu.global.add.u32 [%0], 1;" :: "l"(ctr) : "memory");
            unsigned int v;
            do {
                asm volatile("ld.acquire.gpu.global.u32 %0, [%1];" : "=r"(v) : "l"(ctr) : "memory");
            } while (v < target);
        }
        __syncthreads();
    }
}

// ---------------- K4: output projection (f32x2; 288 threads; smem W) ----------------
__global__ void __launch_bounds__(288) proj_kernel(const float* __restrict__ w_out,
                                                   const float* __restrict__ b_out)
{
    extern __shared__ __align__(16) ull ws2[];   // 5400 duplicated w values (43.2KB)
    const int t = blockIdx.x;
    const int tid = threadIdx.x;                 // 288 = 9 warps
    const int k = tid >> 5;                      // warp = tag
    const int bp = tid & 31;                     // batch pair

    for (int i = tid; i < KKT * 2 * HH; i += 288) ws2[i] = dup2(w_out[i]);
    __syncthreads();

    const ull* hfp = (const ull*)(g_h + (size_t)(t + 1) * HB) + bp;
    const ull* hbp = (const ull*)(g_h + (size_t)(TT + 1) * HB + (size_t)(TT - t) * HB) + bp;
    const ull* wk = ws2 + (size_t)k * (2 * HH);

    ull a0 = dup2(b_out[k]), a1 = 0ull, a2 = 0ull, a3 = 0ull;
#pragma unroll 2
    for (int j = 0; j < HH; j += 4) {
        a0 = fma2(wk[j + 0], hfp[(size_t)(j + 0) * 32], a0);
        a1 = fma2(wk[j + 1], hfp[(size_t)(j + 1) * 32], a1);
        a2 = fma2(wk[j + 2], hfp[(size_t)(j + 2) * 32], a2);
        a3 = fma2(wk[j + 3], hfp[(size_t)(j + 3) * 32], a3);
    }
#pragma unroll 2
    for (int j = 0; j < HH; j += 4) {
        a0 = fma2(wk[HH + j + 0], hbp[(size_t)(j + 0) * 32], a0);
        a1 = fma2(wk[HH + j + 1], hbp[(size_t)(j + 1) * 32], a1);
        a2 = fma2(wk[HH + j + 2], hbp[(size_t)(j + 2) * 32], a2);
        a3 = fma2(wk[HH + j + 3], hbp[(size_t)(j + 3) * 32], a3);
    }
    float2 f0 = u2f(a0), f1 = u2f(a1), f2 = u2f(a2), f3 = u2f(a3);
    float rx = (f0.x + f1.x) + (f2.x + f3.x);
    float ry = (f0.y + f1.y) + (f2.y + f3.y);
    g_emis[(size_t)t * (BB * KKT) + (2 * bp) * KKT + k]     = rx;
    g_emis[(size_t)t * (BB * KKT) + (2 * bp + 1) * KKT + k] = ry;
}

// ---------------- K5: merged Viterbi + CRF (128 CTAs run concurrently) ----------------
__global__ void vitcrf_kernel(const int* __restrict__ tags,
                              const float* __restrict__ start_t, const float* __restrict__ end_t,
                              const float* __restrict__ trans, float* __restrict__ out)
{
    const int b = blockIdx.x & 63;
    const int k = threadIdx.x;
    __shared__ float sc[KKT], ns[KKT], tr[KKT * KKT];
    __shared__ int hist_s[(TT - 1) * KKT];
    for (int i = k; i < KKT * KKT; i += 32) tr[i] = trans[i];
    __syncwarp();

    if (blockIdx.x < BB) {
        if (k < KKT) sc[k] = start_t[k] + g_emis[(size_t)b * KKT + k];
        float enext = (k < KKT) ? __ldcg(&g_emis[(size_t)(BB + b) * KKT + k]) : 0.f;
        __syncwarp();
        for (int t = 1; t < TT; t++) {
            float ecur = enext;
            if (k < KKT && t + 1 < TT)
                enext = __ldcg(&g_emis[((size_t)(t + 1) * BB + b) * KKT + k]);
            if (k < KKT) {
                float best = -1e30f; int arg = 0;
#pragma unroll
                for (int kp = 0; kp < KKT; kp++) {
                    float v = sc[kp] + tr[kp * KKT + k];
                    if (v > best) { best = v; arg = kp; }
                }
                ns[k] = best + ecur;
                hist_s[(t - 1) * KKT + k] = arg;
            }
            __syncwarp();
            if (k < KKT) sc[k] = ns[k];
            __syncwarp();
        }
        if (k == 0) {
            float best = -1e30f; int last = 0;
#pragma unroll
            for (int kk = 0; kk < KKT; kk++) {
                float v = sc[kk] + end_t[kk];
                if (v > best) { best = v; last = kk; }
            }
            out[(size_t)b * TT + (TT - 1)] = (float)last;
            int tag = last;
            for (int t = TT - 2; t >= 0; t--) {
                tag = hist_s[t * KKT + tag];
                out[(size_t)b * TT + t] = (float)tag;
            }
        }
    } else {
        float partn = 0.f;
        for (int t = k; t < TT; t += 32) {
            int ttg = tags[(size_t)b * TT + t];
            if (t == 0) {
                partn += start_t[ttg] + g_emis[(size_t)b * KKT + ttg];
            } else {
                int tp = tags[(size_t)b * TT + t - 1];
                partn += tr[tp * KKT + ttg] + g_emis[((size_t)t * BB + b) * KKT + ttg];
            }
            if (t == TT - 1) partn += end_t[ttg];
        }
#pragma unroll
        for (int off = 16; off; off >>= 1)
            partn += __shfl_xor_sync(0xffffffffu, partn, off);
        float num = partn;

        if (k < KKT) sc[k] = start_t[k] + g_emis[(size_t)b * KKT + k];
        float enext = (k < KKT) ? __ldcg(&g_emis[(size_t)(BB + b) * KKT + k]) : 0.f;
        __syncwarp();
        for (int t = 1; t < TT; t++) {
            float ecur = enext;
            if (k < KKT && t + 1 < TT)
                enext = __ldcg(&g_emis[((size_t)(t + 1) * BB + b) * KKT + k]);
            if (k < KKT) {
                float mx = -1e30f;
#pragma unroll
                for (int kp = 0; kp < KKT; kp++) mx = fmaxf(mx, sc[kp] + tr[kp * KKT + k]);
                float ssum = 0.f;
#pragma unroll
                for (int kp = 0; kp < KKT; kp++) ssum += expf(sc[kp] + tr[kp * KKT + k] - mx);
                ns[k] = mx + logf(ssum) + ecur;
            }
            __syncwarp();
            if (k < KKT) sc[k] = ns[k];
            __syncwarp();
        }
        if (k == 0) {
            float mx = -1e30f;
#pragma unroll
            for (int kk = 0; kk < KKT; kk++) mx = fmaxf(mx, sc[kk] + end_t[kk]);
            float ssum = 0.f;
#pragma unroll
            for (int kk = 0; kk < KKT; kk++) ssum += expf(sc[kk] + end_t[kk] - mx);
            g_lossb[b] = (mx + logf(ssum)) - num;
        }
    }
}

// ---------------- K6: deterministic loss reduction ----------------
__global__ void finalize_kernel(float* __restrict__ out)
{
    if (blockIdx.x == 0 && threadIdx.x == 0) {
        float s = 0.f;
        for (int b = 0; b < BB; b++) s += g_lossb[b];
        out[(size_t)BB * TT] = s;
    }
}

// ---------------- launch ----------------
extern "C" void kernel_launch(void* const* d_in, const int* in_sizes, int n_in,
                              void* d_out, int out_size)
{
    const int*   tokens  = (const int*)  d_in[0];
    const int*   tags    = (const int*)  d_in[1];
    // d_in[2] = mask (all ones by construction; unused)
    const float* emb     = (const float*)d_in[3];
    const float* w_ih_f  = (const float*)d_in[4];
    const float* w_hh_f  = (const float*)d_in[5];
    const float* b_ih_f  = (const float*)d_in[6];
    const float* b_hh_f  = (const float*)d_in[7];
    const float* w_ih_b  = (const float*)d_in[8];
    const float* w_hh_b  = (const float*)d_in[9];
    const float* b_ih_b  = (const float*)d_in[10];
    const float* b_hh_b  = (const float*)d_in[11];
    const float* h0      = (const float*)d_in[12];
    const float* c0      = (const float*)d_in[13];
    const float* w_out   = (const float*)d_in[14];
    const float* b_out   = (const float*)d_in[15];
    const float* start_t = (const float*)d_in[16];
    const float* end_t   = (const float*)d_in[17];
    const float* trans   = (const float*)d_in[18];
    float* out = (float*)d_out;

    const int rec_smem    = SM_TOTF * 4;       // 204544 bytes
    const int gather_smem = 64 * 305 * 4;      // 78080 bytes
    const int proj_smem   = KKT * 2 * HH * 8;  // 43200 bytes
    static int smem_set = 0;
    if (!smem_set) {
        cudaFuncSetAttribute(lstm_rec_kernel, cudaFuncAttributeMaxDynamicSharedMemorySize, rec_smem);
        cudaFuncSetAttribute(gather_kernel, cudaFuncAttributeMaxDynamicSharedMemorySize, gather_smem);
        smem_set = 1;
    }

    prep_kernel<<<150, 256>>>(b_ih_f, b_hh_f, b_ih_b, b_hh_b, h0);
    gather_kernel<<<TT, 256, gather_smem>>>(tokens, emb);
    lstm_rec_kernel<<<2 * NSL, 512, rec_smem>>>(w_hh_f, w_hh_b, w_ih_f, w_ih_b, c0);
    proj_kernel<<<TT, 288, proj_smem>>>(w_out, b_out);
    vitcrf_kernel<<<2 * BB, 32>>>(tags, start_t, end_t, trans, out);
    finalize_kernel<<<1, 1>>>(out);
}

// round 15
// speedup vs baseline: 1.1346x; 1.1346x over previous
#include <cuda_runtime.h>
#include <math.h>

// Problem dims
#define TT   512
#define BB   64
#define HH   300
#define KKT  9
#define G4   1200           // 4*H
#define NCOL 32768          // T*B columns (t*64+b)
#define HB   (HH*BB)        // 19200
#define NSL  75             // slices per direction (4 cols each); grid = 150
#define HROW 68             // padded h_sm row stride (floats); batch quads at {0,16,36,52}
#define PROW 68             // part row stride (floats), same quad layout

typedef unsigned long long ull;

// ---------------- scratch (device globals; no runtime allocation) ----------------
__device__ __align__(16) float g_xT[(size_t)HH * NCOL];
__device__ __align__(16) float g_pre[(size_t)2 * G4 * NCOL];
__device__ __align__(16) float g_h[(size_t)2 * (TT + 1) * HB];   // [dir][t+1][k][b]
__device__ float g_emis[(size_t)TT * BB * KKT];
__device__ float g_bias[2 * G4];
__device__ float g_lossb[BB];
__device__ unsigned int g_bar2[64];                // [0]=fwd ctr, [32]=bwd ctr

// ---------------- helpers ----------------
__device__ __forceinline__ ull dup2(float v) {
    ull r; asm("mov.b64 %0, {%1, %1};" : "=l"(r) : "f"(v)); return r;
}
__device__ __forceinline__ ull fma2(ull a, ull b, ull c) {
    ull d; asm("fma.rn.f32x2 %0, %1, %2, %3;" : "=l"(d) : "l"(a), "l"(b), "l"(c)); return d;
}
__device__ __forceinline__ float2 u2f(ull v) {
    float2 r; asm("mov.b64 {%0, %1}, %2;" : "=f"(r.x), "=f"(r.y) : "l"(v)); return r;
}
__device__ __forceinline__ float sig_(float x) { return 1.0f / (1.0f + __expf(-x)); }
__device__ __forceinline__ float tanh_(float x) {
    float e = __expf(-2.0f * fabsf(x));
    float r = (1.0f - e) / (1.0f + e);
    return copysignf(r, x);
}
__device__ __forceinline__ unsigned int smem_u32(const void* p) {
    unsigned int a;
    asm("{ .reg .u64 t; cvta.to.shared.u64 t, %1; cvt.u32.u64 %0, t; }" : "=r"(a) : "l"(p));
    return a;
}
__device__ __forceinline__ void cpa16(unsigned int dst, const void* src) {
    asm volatile("cp.async.cg.shared.global [%0], [%1], 16;" :: "r"(dst), "l"(src) : "memory");
}
__device__ __forceinline__ void cpa16z(unsigned int dst, const void* src, int srcbytes) {
    asm volatile("cp.async.cg.shared.global [%0], [%1], 16, %2;"
                 :: "r"(dst), "l"(src), "r"(srcbytes) : "memory");
}

// ---------------- K0: prep ----------------
__global__ void prep_kernel(const float* __restrict__ b_ih_f, const float* __restrict__ b_hh_f,
                            const float* __restrict__ b_ih_b, const float* __restrict__ b_hh_b,
                            const float* __restrict__ h0)
{
    int idx = blockIdx.x * blockDim.x + threadIdx.x;
    if (idx < 64) g_bar2[idx] = 0u;
    if (idx < 2 * G4) {
        g_bias[idx] = (idx < G4) ? (b_ih_f[idx] + b_hh_f[idx])
                                 : (b_ih_b[idx - G4] + b_hh_b[idx - G4]);
    }
    if (idx < 2 * HB) {
        int dir = idx / HB;
        int rem = idx - dir * HB;
        int k = rem >> 6;
        int b = rem & 63;
        g_h[(size_t)dir * (TT + 1) * HB + (size_t)k * BB + b] = h0[(size_t)(dir * BB + b) * HH + k];
    }
}

// ---------------- K1: embedding gather (smem transpose; both sides coalesced) ----------------
__global__ void gather_kernel(const int* __restrict__ tokens, const float* __restrict__ emb)
{
    extern __shared__ float xs[];              // [64][305]
    __shared__ int tok[BB];
    const int t = blockIdx.x;
    const int tid = threadIdx.x;               // 256
    if (tid < BB) tok[tid] = tokens[tid * TT + t];
    __syncthreads();

    const int w = tid >> 5, lane = tid & 31;
#pragma unroll
    for (int i = 0; i < 8; i++) {
        int b = w * 8 + i;
        const float* er = emb + (size_t)tok[b] * HH;
        for (int d = lane; d < HH; d += 32) xs[b * 305 + d] = er[d];
    }
    __syncthreads();

    const int b = tid & 63;
    const int dbase = tid >> 6;                // 0..3
    float* dst = g_xT + (size_t)t * BB + b;
    for (int d = dbase; d < HH; d += 4)
        dst[(size_t)d * NCOL] = xs[b * 305 + d];
}

// ---------------- K2: input projection GEMM (f32x2, 2-stage cp.async pipeline) ----------------
#define BK 16
#define NCH 19                        // ceil(300/16)
__global__ void __launch_bounds__(256, 2) gemm_pre_kernel(const float* __restrict__ w_ih_f,
                                                          const float* __restrict__ w_ih_b)
{
    __shared__ __align__(16) ull   As2[2][BK][128];
    __shared__ __align__(16) float Bs[2][BK][128];

    const int m0 = blockIdx.y * 128;
    const int n0 = blockIdx.x * 128;
    const int tid = threadIdx.x;
    const int ty = tid >> 4;
    const int tx = tid & 15;

    const int lm = tid & 127;
    const int ka = (tid >> 7) * 8;
    const int am = m0 + lm;
    const bool amv = (am < 2400);
    const float* wrow = amv ? ((am < G4) ? (w_ih_f + (size_t)am * HH)
                                         : (w_ih_b + (size_t)(am - G4) * HH)) : (const float*)w_ih_f;

    const int nb = (tid & 31) * 4;
    const int kb = tid >> 5;

    ull acc[8][4];
#pragma unroll
    for (int i = 0; i < 8; i++)
#pragma unroll
        for (int j = 0; j < 4; j++) acc[i][j] = 0ull;

    float4 a0, a1;
    {
        int k0 = 0;
        a0 = amv ? *(const float4*)(wrow + k0 + ka) : make_float4(0, 0, 0, 0);
        a1 = amv ? *(const float4*)(wrow + k0 + ka + 4) : make_float4(0, 0, 0, 0);
#pragma unroll
        for (int r = 0; r < 2; r++) {
            int kc = k0 + kb * 2 + r;
            cpa16z(smem_u32(&Bs[0][kb * 2 + r][nb]),
                   g_xT + (size_t)kc * NCOL + n0 + nb, (kc < 300) ? 16 : 0);
        }
        asm volatile("cp.async.commit_group;" ::: "memory");
        As2[0][ka + 0][lm] = dup2(a0.x); As2[0][ka + 1][lm] = dup2(a0.y);
        As2[0][ka + 2][lm] = dup2(a0.z); As2[0][ka + 3][lm] = dup2(a0.w);
        As2[0][ka + 4][lm] = dup2(a1.x); As2[0][ka + 5][lm] = dup2(a1.y);
        As2[0][ka + 6][lm] = dup2(a1.z); As2[0][ka + 7][lm] = dup2(a1.w);
        asm volatile("cp.async.wait_group 0;" ::: "memory");
        __syncthreads();
    }

    int buf = 0;
    for (int ch = 1; ch < NCH; ch++) {
        const int k0 = ch * BK;
        bool v0 = amv && (k0 + ka + 3 < 300);
        bool v1 = amv && (k0 + ka + 7 < 300);
        a0 = v0 ? *(const float4*)(wrow + k0 + ka) : make_float4(0, 0, 0, 0);
        a1 = v1 ? *(const float4*)(wrow + k0 + ka + 4) : make_float4(0, 0, 0, 0);
#pragma unroll
        for (int r = 0; r < 2; r++) {
            int kc = k0 + kb * 2 + r;
            cpa16z(smem_u32(&Bs[buf ^ 1][kb * 2 + r][nb]),
                   g_xT + (size_t)kc * NCOL + n0 + nb, (kc < 300) ? 16 : 0);
        }
        asm volatile("cp.async.commit_group;" ::: "memory");

#pragma unroll
        for (int kk = 0; kk < BK; kk++) {
            ull av[8];
            const ull* ap = &As2[buf][kk][ty * 8];
#pragma unroll
            for (int i = 0; i < 8; i++) av[i] = ap[i];
            ulonglong2 b0 = *(const ulonglong2*)&Bs[buf][kk][tx * 4];
            ulonglong2 b1 = *(const ulonglong2*)&Bs[buf][kk][64 + tx * 4];
#pragma unroll
            for (int i = 0; i < 8; i++) {
                acc[i][0] = fma2(av[i], b0.x, acc[i][0]);
                acc[i][1] = fma2(av[i], b0.y, acc[i][1]);
                acc[i][2] = fma2(av[i], b1.x, acc[i][2]);
                acc[i][3] = fma2(av[i], b1.y, acc[i][3]);
            }
        }
        As2[buf ^ 1][ka + 0][lm] = dup2(a0.x); As2[buf ^ 1][ka + 1][lm] = dup2(a0.y);
        As2[buf ^ 1][ka + 2][lm] = dup2(a0.z); As2[buf ^ 1][ka + 3][lm] = dup2(a0.w);
        As2[buf ^ 1][ka + 4][lm] = dup2(a1.x); As2[buf ^ 1][ka + 5][lm] = dup2(a1.y);
        As2[buf ^ 1][ka + 6][lm] = dup2(a1.z); As2[buf ^ 1][ka + 7][lm] = dup2(a1.w);
        asm volatile("cp.async.wait_group 0;" ::: "memory");
        __syncthreads();
        buf ^= 1;
    }
#pragma unroll
    for (int kk = 0; kk < BK; kk++) {
        ull av[8];
        const ull* ap = &As2[buf][kk][ty * 8];
#pragma unroll
        for (int i = 0; i < 8; i++) av[i] = ap[i];
        ulonglong2 b0 = *(const ulonglong2*)&Bs[buf][kk][tx * 4];
        ulonglong2 b1 = *(const ulonglong2*)&Bs[buf][kk][64 + tx * 4];
#pragma unroll
        for (int i = 0; i < 8; i++) {
            acc[i][0] = fma2(av[i], b0.x, acc[i][0]);
            acc[i][1] = fma2(av[i], b0.y, acc[i][1]);
            acc[i][2] = fma2(av[i], b1.x, acc[i][2]);
            acc[i][3] = fma2(av[i], b1.y, acc[i][3]);
        }
    }

#pragma unroll
    for (int i = 0; i < 8; i++) {
        int m = m0 + ty * 8 + i;
        if (m >= 2400) continue;
        float bvs = g_bias[m];
        float2 v0 = u2f(acc[i][0]), v1 = u2f(acc[i][1]);
        float2 v2 = u2f(acc[i][2]), v3 = u2f(acc[i][3]);
        float* cp = &g_pre[(size_t)m * NCOL + n0];
        *(float4*)(cp + tx * 4)      = make_float4(v0.x + bvs, v0.y + bvs, v1.x + bvs, v1.y + bvs);
        *(float4*)(cp + 64 + tx * 4) = make_float4(v2.x + bvs, v2.y + bvs, v3.x + bvs, v3.y + bvs);
    }
}

// ---------------- K3: persistent LSTM recurrence (R12/R13 best; untouched) ----------------
__global__ void __launch_bounds__(512, 1) lstm_rec_kernel(const float* __restrict__ whh_f,
                                                          const float* __restrict__ whh_b,
                                                          const float* __restrict__ c0)
{
    extern __shared__ __align__(16) float sm_f[];
    float* h_sm = sm_f;                        // [304][HROW]
    float* part = sm_f + 304 * HROW;           // [256][PROW]  (16ks x 16cg)

    const int bid = blockIdx.x;
    const int dir = bid & 1;
    const int s   = bid >> 1;                  // 0..74
    const int colbase = s * 4;

    const int tid  = threadIdx.x;
    const int ks   = tid >> 5;                 // 0..15 (19 k each)
    const int lane = tid & 31;
    const int bq   = lane >> 3;                // 0..3 batch quad (16 each)
    const int cgrp = lane & 7;                 // owns cg = cgrp, cgrp+8
    const int bqf  = (bq < 2) ? bq * 16 : 36 + (bq - 2) * 16;  // {0,16,36,52}

    const float* whh = dir ? whh_b : whh_f;

    // zero pad rows 300..303 (read by ks=15; never staged; W=0 there)
    if (tid < 4 * HROW) h_sm[300 * HROW + tid] = 0.f;

    // W_hh -> registers
    const int cgA = cgrp,      cA = cgA >> 2, gA = cgA & 3;
    const int cgB = cgrp + 8,  cB = cgB >> 2, gB = cgB & 3;
    float WfA[19], WfB[19];
#pragma unroll
    for (int kk = 0; kk < 19; kk++) {
        int k = ks * 19 + kk;
        WfA[kk] = (k < 300) ? whh[(size_t)(gA * HH + colbase + cA) * HH + k] : 0.f;
        WfB[kk] = (k < 300) ? whh[(size_t)(gB * HH + colbase + cB) * HH + k] : 0.f;
    }

    // finalize role (first 256 threads): 1 column per thread
    const int ffc = (tid >> 6) & 3;
    const int ffb = tid & 63;
    const int fcol = (ffb < 32) ? ffb : ffb + 4;
    float cst = 0.f;
    if (tid < 256) cst = c0[(size_t)(dir * BB + ffb) * HH + colbase + ffc];

    __syncthreads();

    float*       ghdir  = g_h + (size_t)dir * (TT + 1) * HB;
    const float* predir = g_pre + (size_t)dir * G4 * NCOL;
    unsigned int* ctr   = &g_bar2[dir * 32];

    const unsigned int hdst0 = smem_u32(h_sm + (size_t)ks * 19 * HROW);
    const float* hbase = h_sm + (size_t)ks * 19 * HROW + bqf;
    float* ppA = part + (size_t)(ks * 16 + cgA) * PROW + bqf;
    float* ppB = part + (size_t)(ks * 16 + cgB) * PROW + bqf;

    unsigned int target = 0;
    for (int t = 0; t < TT; t++) {
        const int tp = dir ? (TT - 1 - t) : t;

        // prefetch pre-activations for finalize (hidden behind the dot)
        float pre0 = 0.f, pre1 = 0.f, pre2 = 0.f, pre3 = 0.f;
        if (tid < 256) {
            const float* pb = predir + (size_t)tp * BB + ffb;
            pre0 = __ldcg(pb + (size_t)(0 * HH + colbase + ffc) * NCOL);
            pre1 = __ldcg(pb + (size_t)(1 * HH + colbase + ffc) * NCOL);
            pre2 = __ldcg(pb + (size_t)(2 * HH + colbase + ffc) * NCOL);
            pre3 = __ldcg(pb + (size_t)(3 * HH + colbase + ffc) * NCOL);
        }

        // warp-local h staging (compile-time trip counts; addresses fold)
        const float4* hsrc = (const float4*)(ghdir + (size_t)t * HB) + ks * 19 * 16;
        if (ks < 15) {
#pragma unroll
            for (int j = 0; j < 9; j++) {
                int i = lane + 32 * j;
                unsigned int dst = hdst0 + (i >> 4) * (HROW * 4) + (i & 15) * 16 + ((i & 8) << 1);
                cpa16(dst, hsrc + i);
            }
            if (lane < 16) {
                int i = lane + 288;
                unsigned int dst = hdst0 + (i >> 4) * (HROW * 4) + (i & 15) * 16 + ((i & 8) << 1);
                cpa16(dst, hsrc + i);
            }
        } else {
#pragma unroll
            for (int j = 0; j < 7; j++) {
                int i = lane + 32 * j;
                unsigned int dst = hdst0 + (i >> 4) * (HROW * 4) + (i & 15) * 16 + ((i & 8) << 1);
                cpa16(dst, hsrc + i);
            }
            if (lane < 16) {
                int i = lane + 224;
                unsigned int dst = hdst0 + (i >> 4) * (HROW * 4) + (i & 15) * 16 + ((i & 8) << 1);
                cpa16(dst, hsrc + i);
            }
        }
        asm volatile("cp.async.commit_group;" ::: "memory");
        asm volatile("cp.async.wait_group 0;" ::: "memory");
        __syncwarp();

        // dot: 19 k x 16 batch x 2 (c,g); h loaded once, reused for both cgs
        ull accA[8], accB[8];
#pragma unroll
        for (int i = 0; i < 8; i++) { accA[i] = 0ull; accB[i] = 0ull; }
#pragma unroll
        for (int kk = 0; kk < 19; kk++) {
            const ulonglong2* hp = (const ulonglong2*)(hbase + kk * HROW);
            ulonglong2 q0 = hp[0], q1 = hp[1], q2 = hp[2], q3 = hp[3];
            ull wA = dup2(WfA[kk]);
            ull wB = dup2(WfB[kk]);
            accA[0] = fma2(wA, q0.x, accA[0]); accA[1] = fma2(wA, q0.y, accA[1]);
            accA[2] = fma2(wA, q1.x, accA[2]); accA[3] = fma2(wA, q1.y, accA[3]);
            accA[4] = fma2(wA, q2.x, accA[4]); accA[5] = fma2(wA, q2.y, accA[5]);
            accA[6] = fma2(wA, q3.x, accA[6]); accA[7] = fma2(wA, q3.y, accA[7]);
            accB[0] = fma2(wB, q0.x, accB[0]); accB[1] = fma2(wB, q0.y, accB[1]);
            accB[2] = fma2(wB, q1.x, accB[2]); accB[3] = fma2(wB, q1.y, accB[3]);
            accB[4] = fma2(wB, q2.x, accB[4]); accB[5] = fma2(wB, q2.y, accB[5]);
            accB[6] = fma2(wB, q3.x, accB[6]); accB[7] = fma2(wB, q3.y, accB[7]);
        }

        // store partials (conflict-free layout)
#pragma unroll
        for (int j = 0; j < 4; j++) {
            ulonglong2 v; v.x = accA[2 * j]; v.y = accA[2 * j + 1];
            *(ulonglong2*)(ppA + j * 4) = v;
        }
#pragma unroll
        for (int j = 0; j < 4; j++) {
            ulonglong2 v; v.x = accB[2 * j]; v.y = accB[2 * j + 1];
            *(ulonglong2*)(ppB + j * 4) = v;
        }
        __syncthreads();

        // finalize: sum 16 ks-partials + pre, gates, write h(t+1)
        if (tid < 256) {
            float gv0 = pre0, gv1 = pre1, gv2 = pre2, gv3 = pre3;
#pragma unroll
            for (int kss = 0; kss < 16; kss++) {
                const float* pr = part + (size_t)(kss * 16 + ffc * 4) * PROW + fcol;
                gv0 += pr[0];
                gv1 += pr[PROW];
                gv2 += pr[2 * PROW];
                gv3 += pr[3 * PROW];
            }
            float ig = sig_(gv0), fg = sig_(gv1), gt = tanh_(gv2), og = sig_(gv3);
            cst = fg * cst + ig * gt;
            ghdir[(size_t)(t + 1) * HB + (size_t)(colbase + ffc) * BB + ffb] = og * tanh_(cst);
        }

        if (t == TT - 1) break;    // kernel boundary is the final sync

        // per-direction grid barrier (single counter; release-arrive + acquire-poll)
        target += NSL;
        __syncthreads();
        if (tid == 0) {
            asm volatile("red.release.gpu.global.add.u32 [%0], 1;" :: "l"(ctr) : "memory");
            unsigned int v;
            do {
                asm volatile("ld.acquire.gpu.global.u32 %0, [%1];" : "=r"(v) : "l"(ctr) : "memory");
            } while (v < target);
        }
        __syncthreads();
    }
}

// ---------------- K4: output projection v3 (chunked smem h staging; 9x less gmem) ----------------
#define PJC 75          // rows per chunk (300 = 4 chunks per direction half)
__global__ void __launch_bounds__(288) proj_kernel(const float* __restrict__ w_out,
                                                   const float* __restrict__ b_out)
{
    extern __shared__ __align__(16) ull ws2[];       // 5400 dup'd w (43.2KB)
    float* hs = (float*)(ws2 + KKT * 2 * HH);        // [PJC][64]  (19.2KB)
    const int t = blockIdx.x;
    const int tid = threadIdx.x;                     // 288 = 9 warps
    const int k = tid >> 5;                          // warp = tag
    const int bp = tid & 31;                         // batch pair

    for (int i = tid; i < KKT * 2 * HH; i += 288) ws2[i] = dup2(w_out[i]);

    const float* hfg = g_h + (size_t)(t + 1) * HB;
    const float* hbg = g_h + (size_t)(TT + 1) * HB + (size_t)(TT - t) * HB;
    const ull* wk = ws2 + (size_t)k * (2 * HH);
    const ull* hp0 = (const ull*)hs + bp;

    ull acc[4];
    acc[0] = dup2(b_out[k]); acc[1] = 0ull; acc[2] = 0ull; acc[3] = 0ull;

    // forward half: 4 chunks of 75 rows (accumulation order identical to v2)
#pragma unroll
    for (int c = 0; c < 4; c++) {
        __syncthreads();
        const float4* src = (const float4*)(hfg + (size_t)c * PJC * BB);
        for (int i = tid; i < PJC * 16; i += 288) ((float4*)hs)[i] = src[i];
        __syncthreads();
#pragma unroll 4
        for (int j = 0; j < PJC; j++) {
            int jj = c * PJC + j;
            acc[jj & 3] = fma2(wk[jj], hp0[j * 32], acc[jj & 3]);
        }
    }
    // backward half
#pragma unroll
    for (int c = 0; c < 4; c++) {
        __syncthreads();
        const float4* src = (const float4*)(hbg + (size_t)c * PJC * BB);
        for (int i = tid; i < PJC * 16; i += 288) ((float4*)hs)[i] = src[i];
        __syncthreads();
#pragma unroll 4
        for (int j = 0; j < PJC; j++) {
            int jj = c * PJC + j;
            acc[jj & 3] = fma2(wk[HH + jj], hp0[j * 32], acc[jj & 3]);
        }
    }

    float2 f0 = u2f(acc[0]), f1 = u2f(acc[1]), f2 = u2f(acc[2]), f3 = u2f(acc[3]);
    float rx = (f0.x + f1.x) + (f2.x + f3.x);
    float ry = (f0.y + f1.y) + (f2.y + f3.y);
    g_emis[(size_t)t * (BB * KKT) + (2 * bp) * KKT + k]     = rx;
    g_emis[(size_t)t * (BB * KKT) + (2 * bp + 1) * KKT + k] = ry;
}

// ---------------- K5: merged Viterbi + CRF (128 CTAs run concurrently) ----------------
__global__ void vitcrf_kernel(const int* __restrict__ tags,
                              const float* __restrict__ start_t, const float* __restrict__ end_t,
                              const float* __restrict__ trans, float* __restrict__ out)
{
    const int b = blockIdx.x & 63;
    const int k = threadIdx.x;
    __shared__ float sc[KKT], ns[KKT], tr[KKT * KKT];
    __shared__ int hist_s[(TT - 1) * KKT];
    for (int i = k; i < KKT * KKT; i += 32) tr[i] = trans[i];
    __syncwarp();

    if (blockIdx.x < BB) {
        if (k < KKT) sc[k] = start_t[k] + g_emis[(size_t)b * KKT + k];
        float enext = (k < KKT) ? __ldcg(&g_emis[(size_t)(BB + b) * KKT + k]) : 0.f;
        __syncwarp();
        for (int t = 1; t < TT; t++) {
            float ecur = enext;
            if (k < KKT && t + 1 < TT)
                enext = __ldcg(&g_emis[((size_t)(t + 1) * BB + b) * KKT + k]);
            if (k < KKT) {
                float best = -1e30f; int arg = 0;
#pragma unroll
                for (int kp = 0; kp < KKT; kp++) {
                    float v = sc[kp] + tr[kp * KKT + k];
                    if (v > best) { best = v; arg = kp; }
                }
                ns[k] = best + ecur;
                hist_s[(t - 1) * KKT + k] = arg;
            }
            __syncwarp();
            if (k < KKT) sc[k] = ns[k];
            __syncwarp();
        }
        if (k == 0) {
            float best = -1e30f; int last = 0;
#pragma unroll
            for (int kk = 0; kk < KKT; kk++) {
                float v = sc[kk] + end_t[kk];
                if (v > best) { best = v; last = kk; }
            }
            out[(size_t)b * TT + (TT - 1)] = (float)last;
            int tag = last;
            for (int t = TT - 2; t >= 0; t--) {
                tag = hist_s[t * KKT + tag];
                out[(size_t)b * TT + t] = (float)tag;
            }
        }
    } else {
        float partn = 0.f;
        for (int t = k; t < TT; t += 32) {
            int ttg = tags[(size_t)b * TT + t];
            if (t == 0) {
                partn += start_t[ttg] + g_emis[(size_t)b * KKT + ttg];
            } else {
                int tp = tags[(size_t)b * TT + t - 1];
                partn += tr[tp * KKT + ttg] + g_emis[((size_t)t * BB + b) * KKT + ttg];
            }
            if (t == TT - 1) partn += end_t[ttg];
        }
#pragma unroll
        for (int off = 16; off; off >>= 1)
            partn += __shfl_xor_sync(0xffffffffu, partn, off);
        float num = partn;

        if (k < KKT) sc[k] = start_t[k] + g_emis[(size_t)b * KKT + k];
        float enext = (k < KKT) ? __ldcg(&g_emis[(size_t)(BB + b) * KKT + k]) : 0.f;
        __syncwarp();
        for (int t = 1; t < TT; t++) {
            float ecur = enext;
            if (k < KKT && t + 1 < TT)
                enext = __ldcg(&g_emis[((size_t)(t + 1) * BB + b) * KKT + k]);
            if (k < KKT) {
                float mx = -1e30f;
#pragma unroll
                for (int kp = 0; kp < KKT; kp++) mx = fmaxf(mx, sc[kp] + tr[kp * KKT + k]);
                float ssum = 0.f;
#pragma unroll
                for (int kp = 0; kp < KKT; kp++) ssum += expf(sc[kp] + tr[kp * KKT + k] - mx);
                ns[k] = mx + logf(ssum) + ecur;
            }
            __syncwarp();
            if (k < KKT) sc[k] = ns[k];
            __syncwarp();
        }
        if (k == 0) {
            float mx = -1e30f;
#pragma unroll
            for (int kk = 0; kk < KKT; kk++) mx = fmaxf(mx, sc[kk] + end_t[kk]);
            float ssum = 0.f;
#pragma unroll
            for (int kk = 0; kk < KKT; kk++) ssum += expf(sc[kk] + end_t[kk] - mx);
            g_lossb[b] = (mx + logf(ssum)) - num;
        }
    }
}

// ---------------- K6: deterministic loss reduction ----------------
__global__ void finalize_kernel(float* __restrict__ out)
{
    if (blockIdx.x == 0 && threadIdx.x == 0) {
        float s = 0.f;
        for (int b = 0; b < BB; b++) s += g_lossb[b];
        out[(size_t)BB * TT] = s;
    }
}

// ---------------- launch ----------------
extern "C" void kernel_launch(void* const* d_in, const int* in_sizes, int n_in,
                              void* d_out, int out_size)
{
    const int*   tokens  = (const int*)  d_in[0];
    const int*   tags    = (const int*)  d_in[1];
    // d_in[2] = mask (all ones by construction; unused)
    const float* emb     = (const float*)d_in[3];
    const float* w_ih_f  = (const float*)d_in[4];
    const float* w_hh_f  = (const float*)d_in[5];
    const float* b_ih_f  = (const float*)d_in[6];
    const float* b_hh_f  = (const float*)d_in[7];
    const float* w_ih_b  = (const float*)d_in[8];
    const float* w_hh_b  = (const float*)d_in[9];
    const float* b_ih_b  = (const float*)d_in[10];
    const float* b_hh_b  = (const float*)d_in[11];
    const float* h0      = (const float*)d_in[12];
    const float* c0      = (const float*)d_in[13];
    const float* w_out   = (const float*)d_in[14];
    const float* b_out   = (const float*)d_in[15];
    const float* start_t = (const float*)d_in[16];
    const float* end_t   = (const float*)d_in[17];
    const float* trans   = (const float*)d_in[18];
    float* out = (float*)d_out;

    const int rec_smem    = (304 * HROW + 256 * PROW) * 4;   // 152320 bytes
    const int gather_smem = 64 * 305 * 4;                    // 78080 bytes
    const int proj_smem   = KKT * 2 * HH * 8 + PJC * 64 * 4; // 62400 bytes
    static int smem_set = 0;
    if (!smem_set) {
        cudaFuncSetAttribute(lstm_rec_kernel, cudaFuncAttributeMaxDynamicSharedMemorySize, rec_smem);
        cudaFuncSetAttribute(gather_kernel, cudaFuncAttributeMaxDynamicSharedMemorySize, gather_smem);
        cudaFuncSetAttribute(proj_kernel, cudaFuncAttributeMaxDynamicSharedMemorySize, proj_smem);
        smem_set = 1;
    }

    prep_kernel<<<150, 256>>>(b_ih_f, b_hh_f, b_ih_b, b_hh_b, h0);
    gather_kernel<<<TT, 256, gather_smem>>>(tokens, emb);
    gemm_pre_kernel<<<dim3(NCOL / 128, 19), 256>>>(w_ih_f, w_ih_b);
    lstm_rec_kernel<<<2 * NSL, 512, rec_smem>>>(w_hh_f, w_hh_b, c0);
    proj_kernel<<<TT, 288, proj_smem>>>(w_out, b_out);
    vitcrf_kernel<<<2 * BB, 32>>>(tags, start_t, end_t, trans, out);
    finalize_kernel<<<1, 1>>>(out);
}

// round 16
// speedup vs baseline: 1.1362x; 1.0014x over previous
#include <cuda_runtime.h>
#include <math.h>

// Problem dims
#define TT   512
#define BB   64
#define HH   300
#define KKT  9
#define G4   1200           // 4*H
#define NCOL 32768          // T*B columns (t*64+b)
#define HB   (HH*BB)        // 19200
#define NSL  75             // slices per direction (4 cols each); grid = 150
#define HROW 68             // padded h_sm row stride (floats); batch quads at {0,16,36,52}
#define PROW 68             // part row stride (floats), same quad layout

typedef unsigned long long ull;

// ---------------- scratch (device globals; no runtime allocation) ----------------
__device__ __align__(16) float g_xT[(size_t)HH * NCOL];
__device__ __align__(16) float g_pre[(size_t)2 * G4 * NCOL];
__device__ __align__(16) float g_h[(size_t)2 * (TT + 1) * HB];   // [dir][t+1][k][b]
__device__ float g_emis[(size_t)TT * BB * KKT];
__device__ float g_bias[2 * G4];
__device__ float g_lossb[BB];
__device__ unsigned int g_bar2[64];                // [0]=fwd ctr, [32]=bwd ctr

// ---------------- helpers ----------------
__device__ __forceinline__ ull dup2(float v) {
    ull r; asm("mov.b64 %0, {%1, %1};" : "=l"(r) : "f"(v)); return r;
}
__device__ __forceinline__ ull fma2(ull a, ull b, ull c) {
    ull d; asm("fma.rn.f32x2 %0, %1, %2, %3;" : "=l"(d) : "l"(a), "l"(b), "l"(c)); return d;
}
__device__ __forceinline__ float2 u2f(ull v) {
    float2 r; asm("mov.b64 {%0, %1}, %2;" : "=f"(r.x), "=f"(r.y) : "l"(v)); return r;
}
__device__ __forceinline__ float sig_(float x) { return 1.0f / (1.0f + __expf(-x)); }
__device__ __forceinline__ float tanh_(float x) {
    float e = __expf(-2.0f * fabsf(x));
    float r = (1.0f - e) / (1.0f + e);
    return copysignf(r, x);
}
__device__ __forceinline__ unsigned int smem_u32(const void* p) {
    unsigned int a;
    asm("{ .reg .u64 t; cvta.to.shared.u64 t, %1; cvt.u32.u64 %0, t; }" : "=r"(a) : "l"(p));
    return a;
}
__device__ __forceinline__ void cpa16(unsigned int dst, const void* src) {
    asm volatile("cp.async.cg.shared.global [%0], [%1], 16;" :: "r"(dst), "l"(src) : "memory");
}
__device__ __forceinline__ void cpa16z(unsigned int dst, const void* src, int srcbytes) {
    asm volatile("cp.async.cg.shared.global [%0], [%1], 16, %2;"
                 :: "r"(dst), "l"(src), "r"(srcbytes) : "memory");
}

// ---------------- K0: prep ----------------
__global__ void prep_kernel(const float* __restrict__ b_ih_f, const float* __restrict__ b_hh_f,
                            const float* __restrict__ b_ih_b, const float* __restrict__ b_hh_b,
                            const float* __restrict__ h0)
{
    int idx = blockIdx.x * blockDim.x + threadIdx.x;
    if (idx < 64) g_bar2[idx] = 0u;
    if (idx < 2 * G4) {
        g_bias[idx] = (idx < G4) ? (b_ih_f[idx] + b_hh_f[idx])
                                 : (b_ih_b[idx - G4] + b_hh_b[idx - G4]);
    }
    if (idx < 2 * HB) {
        int dir = idx / HB;
        int rem = idx - dir * HB;
        int k = rem >> 6;
        int b = rem & 63;
        g_h[(size_t)dir * (TT + 1) * HB + (size_t)k * BB + b] = h0[(size_t)(dir * BB + b) * HH + k];
    }
}

// ---------------- K1: embedding gather (smem transpose; both sides coalesced) ----------------
__global__ void gather_kernel(const int* __restrict__ tokens, const float* __restrict__ emb)
{
    extern __shared__ float xs[];              // [64][305]
    __shared__ int tok[BB];
    const int t = blockIdx.x;
    const int tid = threadIdx.x;               // 256
    if (tid < BB) tok[tid] = tokens[tid * TT + t];
    __syncthreads();

    const int w = tid >> 5, lane = tid & 31;
#pragma unroll
    for (int i = 0; i < 8; i++) {
        int b = w * 8 + i;
        const float* er = emb + (size_t)tok[b] * HH;
        for (int d = lane; d < HH; d += 32) xs[b * 305 + d] = er[d];
    }
    __syncthreads();

    const int b = tid & 63;
    const int dbase = tid >> 6;                // 0..3
    float* dst = g_xT + (size_t)t * BB + b;
    for (int d = dbase; d < HH; d += 4)
        dst[(size_t)d * NCOL] = xs[b * 305 + d];
}

// ---------------- K2: input projection GEMM (f32x2, 2-stage cp.async pipeline) ----------------
#define BK 16
#define NCH 19                        // ceil(300/16)
__global__ void __launch_bounds__(256, 2) gemm_pre_kernel(const float* __restrict__ w_ih_f,
                                                          const float* __restrict__ w_ih_b)
{
    __shared__ __align__(16) ull   As2[2][BK][128];
    __shared__ __align__(16) float Bs[2][BK][128];

    const int m0 = blockIdx.y * 128;
    const int n0 = blockIdx.x * 128;
    const int tid = threadIdx.x;
    const int ty = tid >> 4;
    const int tx = tid & 15;

    const int lm = tid & 127;
    const int ka = (tid >> 7) * 8;
    const int am = m0 + lm;
    const bool amv = (am < 2400);
    const float* wrow = amv ? ((am < G4) ? (w_ih_f + (size_t)am * HH)
                                         : (w_ih_b + (size_t)(am - G4) * HH)) : (const float*)w_ih_f;

    const int nb = (tid & 31) * 4;
    const int kb = tid >> 5;

    ull acc[8][4];
#pragma unroll
    for (int i = 0; i < 8; i++)
#pragma unroll
        for (int j = 0; j < 4; j++) acc[i][j] = 0ull;

    float4 a0, a1;
    {
        int k0 = 0;
        a0 = amv ? *(const float4*)(wrow + k0 + ka) : make_float4(0, 0, 0, 0);
        a1 = amv ? *(const float4*)(wrow + k0 + ka + 4) : make_float4(0, 0, 0, 0);
#pragma unroll
        for (int r = 0; r < 2; r++) {
            int kc = k0 + kb * 2 + r;
            cpa16z(smem_u32(&Bs[0][kb * 2 + r][nb]),
                   g_xT + (size_t)kc * NCOL + n0 + nb, (kc < 300) ? 16 : 0);
        }
        asm volatile("cp.async.commit_group;" ::: "memory");
        As2[0][ka + 0][lm] = dup2(a0.x); As2[0][ka + 1][lm] = dup2(a0.y);
        As2[0][ka + 2][lm] = dup2(a0.z); As2[0][ka + 3][lm] = dup2(a0.w);
        As2[0][ka + 4][lm] = dup2(a1.x); As2[0][ka + 5][lm] = dup2(a1.y);
        As2[0][ka + 6][lm] = dup2(a1.z); As2[0][ka + 7][lm] = dup2(a1.w);
        asm volatile("cp.async.wait_group 0;" ::: "memory");
        __syncthreads();
    }

    int buf = 0;
    for (int ch = 1; ch < NCH; ch++) {
        const int k0 = ch * BK;
        bool v0 = amv && (k0 + ka + 3 < 300);
        bool v1 = amv && (k0 + ka + 7 < 300);
        a0 = v0 ? *(const float4*)(wrow + k0 + ka) : make_float4(0, 0, 0, 0);
        a1 = v1 ? *(const float4*)(wrow + k0 + ka + 4) : make_float4(0, 0, 0, 0);
#pragma unroll
        for (int r = 0; r < 2; r++) {
            int kc = k0 + kb * 2 + r;
            cpa16z(smem_u32(&Bs[buf ^ 1][kb * 2 + r][nb]),
                   g_xT + (size_t)kc * NCOL + n0 + nb, (kc < 300) ? 16 : 0);
        }
        asm volatile("cp.async.commit_group;" ::: "memory");

#pragma unroll
        for (int kk = 0; kk < BK; kk++) {
            ull av[8];
            const ull* ap = &As2[buf][kk][ty * 8];
#pragma unroll
            for (int i = 0; i < 8; i++) av[i] = ap[i];
            ulonglong2 b0 = *(const ulonglong2*)&Bs[buf][kk][tx * 4];
            ulonglong2 b1 = *(const ulonglong2*)&Bs[buf][kk][64 + tx * 4];
#pragma unroll
            for (int i = 0; i < 8; i++) {
                acc[i][0] = fma2(av[i], b0.x, acc[i][0]);
                acc[i][1] = fma2(av[i], b0.y, acc[i][1]);
                acc[i][2] = fma2(av[i], b1.x, acc[i][2]);
                acc[i][3] = fma2(av[i], b1.y, acc[i][3]);
            }
        }
        As2[buf ^ 1][ka + 0][lm] = dup2(a0.x); As2[buf ^ 1][ka + 1][lm] = dup2(a0.y);
        As2[buf ^ 1][ka + 2][lm] = dup2(a0.z); As2[buf ^ 1][ka + 3][lm] = dup2(a0.w);
        As2[buf ^ 1][ka + 4][lm] = dup2(a1.x); As2[buf ^ 1][ka + 5][lm] = dup2(a1.y);
        As2[buf ^ 1][ka + 6][lm] = dup2(a1.z); As2[buf ^ 1][ka + 7][lm] = dup2(a1.w);
        asm volatile("cp.async.wait_group 0;" ::: "memory");
        __syncthreads();
        buf ^= 1;
    }
#pragma unroll
    for (int kk = 0; kk < BK; kk++) {
        ull av[8];
        const ull* ap = &As2[buf][kk][ty * 8];
#pragma unroll
        for (int i = 0; i < 8; i++) av[i] = ap[i];
        ulonglong2 b0 = *(const ulonglong2*)&Bs[buf][kk][tx * 4];
        ulonglong2 b1 = *(const ulonglong2*)&Bs[buf][kk][64 + tx * 4];
#pragma unroll
        for (int i = 0; i < 8; i++) {
            acc[i][0] = fma2(av[i], b0.x, acc[i][0]);
            acc[i][1] = fma2(av[i], b0.y, acc[i][1]);
            acc[i][2] = fma2(av[i], b1.x, acc[i][2]);
            acc[i][3] = fma2(av[i], b1.y, acc[i][3]);
        }
    }

#pragma unroll
    for (int i = 0; i < 8; i++) {
        int m = m0 + ty * 8 + i;
        if (m >= 2400) continue;
        float bvs = g_bias[m];
        float2 v0 = u2f(acc[i][0]), v1 = u2f(acc[i][1]);
        float2 v2 = u2f(acc[i][2]), v3 = u2f(acc[i][3]);
        float* cp = &g_pre[(size_t)m * NCOL + n0];
        *(float4*)(cp + tx * 4)      = make_float4(v0.x + bvs, v0.y + bvs, v1.x + bvs, v1.y + bvs);
        *(float4*)(cp + 64 + tx * 4) = make_float4(v2.x + bvs, v2.y + bvs, v3.x + bvs, v3.y + bvs);
    }
}

// ---------------- K3: persistent LSTM recurrence (R12/R13 best; untouched) ----------------
__global__ void __launch_bounds__(512, 1) lstm_rec_kernel(const float* __restrict__ whh_f,
                                                          const float* __restrict__ whh_b,
                                                          const float* __restrict__ c0)
{
    extern __shared__ __align__(16) float sm_f[];
    float* h_sm = sm_f;                        // [304][HROW]
    float* part = sm_f + 304 * HROW;           // [256][PROW]  (16ks x 16cg)

    const int bid = blockIdx.x;
    const int dir = bid & 1;
    const int s   = bid >> 1;                  // 0..74
    const int colbase = s * 4;

    const int tid  = threadIdx.x;
    const int ks   = tid >> 5;                 // 0..15 (19 k each)
    const int lane = tid & 31;
    const int bq   = lane >> 3;                // 0..3 batch quad (16 each)
    const int cgrp = lane & 7;                 // owns cg = cgrp, cgrp+8
    const int bqf  = (bq < 2) ? bq * 16 : 36 + (bq - 2) * 16;  // {0,16,36,52}

    const float* whh = dir ? whh_b : whh_f;

    // zero pad rows 300..303 (read by ks=15; never staged; W=0 there)
    if (tid < 4 * HROW) h_sm[300 * HROW + tid] = 0.f;

    // W_hh -> registers
    const int cgA = cgrp,      cA = cgA >> 2, gA = cgA & 3;
    const int cgB = cgrp + 8,  cB = cgB >> 2, gB = cgB & 3;
    float WfA[19], WfB[19];
#pragma unroll
    for (int kk = 0; kk < 19; kk++) {
        int k = ks * 19 + kk;
        WfA[kk] = (k < 300) ? whh[(size_t)(gA * HH + colbase + cA) * HH + k] : 0.f;
        WfB[kk] = (k < 300) ? whh[(size_t)(gB * HH + colbase + cB) * HH + k] : 0.f;
    }

    // finalize role (first 256 threads): 1 column per thread
    const int ffc = (tid >> 6) & 3;
    const int ffb = tid & 63;
    const int fcol = (ffb < 32) ? ffb : ffb + 4;
    float cst = 0.f;
    if (tid < 256) cst = c0[(size_t)(dir * BB + ffb) * HH + colbase + ffc];

    __syncthreads();

    float*       ghdir  = g_h + (size_t)dir * (TT + 1) * HB;
    const float* predir = g_pre + (size_t)dir * G4 * NCOL;
    unsigned int* ctr   = &g_bar2[dir * 32];

    const unsigned int hdst0 = smem_u32(h_sm + (size_t)ks * 19 * HROW);
    const float* hbase = h_sm + (size_t)ks * 19 * HROW + bqf;
    float* ppA = part + (size_t)(ks * 16 + cgA) * PROW + bqf;
    float* ppB = part + (size_t)(ks * 16 + cgB) * PROW + bqf;

    unsigned int target = 0;
    for (int t = 0; t < TT; t++) {
        const int tp = dir ? (TT - 1 - t) : t;

        // prefetch pre-activations for finalize (hidden behind the dot)
        float pre0 = 0.f, pre1 = 0.f, pre2 = 0.f, pre3 = 0.f;
        if (tid < 256) {
            const float* pb = predir + (size_t)tp * BB + ffb;
            pre0 = __ldcg(pb + (size_t)(0 * HH + colbase + ffc) * NCOL);
            pre1 = __ldcg(pb + (size_t)(1 * HH + colbase + ffc) * NCOL);
            pre2 = __ldcg(pb + (size_t)(2 * HH + colbase + ffc) * NCOL);
            pre3 = __ldcg(pb + (size_t)(3 * HH + colbase + ffc) * NCOL);
        }

        // warp-local h staging (compile-time trip counts; addresses fold)
        const float4* hsrc = (const float4*)(ghdir + (size_t)t * HB) + ks * 19 * 16;
        if (ks < 15) {
#pragma unroll
            for (int j = 0; j < 9; j++) {
                int i = lane + 32 * j;
                unsigned int dst = hdst0 + (i >> 4) * (HROW * 4) + (i & 15) * 16 + ((i & 8) << 1);
                cpa16(dst, hsrc + i);
            }
            if (lane < 16) {
                int i = lane + 288;
                unsigned int dst = hdst0 + (i >> 4) * (HROW * 4) + (i & 15) * 16 + ((i & 8) << 1);
                cpa16(dst, hsrc + i);
            }
        } else {
#pragma unroll
            for (int j = 0; j < 7; j++) {
                int i = lane + 32 * j;
                unsigned int dst = hdst0 + (i >> 4) * (HROW * 4) + (i & 15) * 16 + ((i & 8) << 1);
                cpa16(dst, hsrc + i);
            }
            if (lane < 16) {
                int i = lane + 224;
                unsigned int dst = hdst0 + (i >> 4) * (HROW * 4) + (i & 15) * 16 + ((i & 8) << 1);
                cpa16(dst, hsrc + i);
            }
        }
        asm volatile("cp.async.commit_group;" ::: "memory");
        asm volatile("cp.async.wait_group 0;" ::: "memory");
        __syncwarp();

        // dot: 19 k x 16 batch x 2 (c,g); h loaded once, reused for both cgs
        ull accA[8], accB[8];
#pragma unroll
        for (int i = 0; i < 8; i++) { accA[i] = 0ull; accB[i] = 0ull; }
#pragma unroll
        for (int kk = 0; kk < 19; kk++) {
            const ulonglong2* hp = (const ulonglong2*)(hbase + kk * HROW);
            ulonglong2 q0 = hp[0], q1 = hp[1], q2 = hp[2], q3 = hp[3];
            ull wA = dup2(WfA[kk]);
            ull wB = dup2(WfB[kk]);
            accA[0] = fma2(wA, q0.x, accA[0]); accA[1] = fma2(wA, q0.y, accA[1]);
            accA[2] = fma2(wA, q1.x, accA[2]); accA[3] = fma2(wA, q1.y, accA[3]);
            accA[4] = fma2(wA, q2.x, accA[4]); accA[5] = fma2(wA, q2.y, accA[5]);
            accA[6] = fma2(wA, q3.x, accA[6]); accA[7] = fma2(wA, q3.y, accA[7]);
            accB[0] = fma2(wB, q0.x, accB[0]); accB[1] = fma2(wB, q0.y, accB[1]);
            accB[2] = fma2(wB, q1.x, accB[2]); accB[3] = fma2(wB, q1.y, accB[3]);
            accB[4] = fma2(wB, q2.x, accB[4]); accB[5] = fma2(wB, q2.y, accB[5]);
            accB[6] = fma2(wB, q3.x, accB[6]); accB[7] = fma2(wB, q3.y, accB[7]);
        }

        // store partials (conflict-free layout)
#pragma unroll
        for (int j = 0; j < 4; j++) {
            ulonglong2 v; v.x = accA[2 * j]; v.y = accA[2 * j + 1];
            *(ulonglong2*)(ppA + j * 4) = v;
        }
#pragma unroll
        for (int j = 0; j < 4; j++) {
            ulonglong2 v; v.x = accB[2 * j]; v.y = accB[2 * j + 1];
            *(ulonglong2*)(ppB + j * 4) = v;
        }
        __syncthreads();

        // finalize: sum 16 ks-partials + pre, gates, write h(t+1)
        if (tid < 256) {
            float gv0 = pre0, gv1 = pre1, gv2 = pre2, gv3 = pre3;
#pragma unroll
            for (int kss = 0; kss < 16; kss++) {
                const float* pr = part + (size_t)(kss * 16 + ffc * 4) * PROW + fcol;
                gv0 += pr[0];
                gv1 += pr[PROW];
                gv2 += pr[2 * PROW];
                gv3 += pr[3 * PROW];
            }
            float ig = sig_(gv0), fg = sig_(gv1), gt = tanh_(gv2), og = sig_(gv3);
            cst = fg * cst + ig * gt;
            ghdir[(size_t)(t + 1) * HB + (size_t)(colbase + ffc) * BB + ffb] = og * tanh_(cst);
        }

        if (t == TT - 1) break;    // kernel boundary is the final sync

        // per-direction grid barrier (single counter; release-arrive + acquire-poll)
        target += NSL;
        __syncthreads();
        if (tid == 0) {
            asm volatile("red.release.gpu.global.add.u32 [%0], 1;" :: "l"(ctr) : "memory");
            unsigned int v;
            do {
                asm volatile("ld.acquire.gpu.global.u32 %0, [%1];" : "=r"(v) : "l"(ctr) : "memory");
            } while (v < target);
        }
        __syncthreads();
    }
}

// ---------------- K4: output projection v3 (chunked smem h staging; 9x less gmem) ----------------
#define PJC 75          // rows per chunk (300 = 4 chunks per direction half)
__global__ void __launch_bounds__(288) proj_kernel(const float* __restrict__ w_out,
                                                   const float* __restrict__ b_out)
{
    extern __shared__ __align__(16) ull ws2[];       // 5400 dup'd w (43.2KB)
    float* hs = (float*)(ws2 + KKT * 2 * HH);        // [PJC][64]  (19.2KB)
    const int t = blockIdx.x;
    const int tid = threadIdx.x;                     // 288 = 9 warps
    const int k = tid >> 5;                          // warp = tag
    const int bp = tid & 31;                         // batch pair

    for (int i = tid; i < KKT * 2 * HH; i += 288) ws2[i] = dup2(w_out[i]);

    const float* hfg = g_h + (size_t)(t + 1) * HB;
    const float* hbg = g_h + (size_t)(TT + 1) * HB + (size_t)(TT - t) * HB;
    const ull* wk = ws2 + (size_t)k * (2 * HH);
    const ull* hp0 = (const ull*)hs + bp;

    ull acc[4];
    acc[0] = dup2(b_out[k]); acc[1] = 0ull; acc[2] = 0ull; acc[3] = 0ull;

    // forward half: 4 chunks of 75 rows (accumulation order identical to v2)
#pragma unroll
    for (int c = 0; c < 4; c++) {
        __syncthreads();
        const float4* src = (const float4*)(hfg + (size_t)c * PJC * BB);
        for (int i = tid; i < PJC * 16; i += 288) ((float4*)hs)[i] = src[i];
        __syncthreads();
#pragma unroll 4
        for (int j = 0; j < PJC; j++) {
            int jj = c * PJC + j;
            acc[jj & 3] = fma2(wk[jj], hp0[j * 32], acc[jj & 3]);
        }
    }
    // backward half
#pragma unroll
    for (int c = 0; c < 4; c++) {
        __syncthreads();
        const float4* src = (const float4*)(hbg + (size_t)c * PJC * BB);
        for (int i = tid; i < PJC * 16; i += 288) ((float4*)hs)[i] = src[i];
        __syncthreads();
#pragma unroll 4
        for (int j = 0; j < PJC; j++) {
            int jj = c * PJC + j;
            acc[jj & 3] = fma2(wk[HH + jj], hp0[j * 32], acc[jj & 3]);
        }
    }

    float2 f0 = u2f(acc[0]), f1 = u2f(acc[1]), f2 = u2f(acc[2]), f3 = u2f(acc[3]);
    float rx = (f0.x + f1.x) + (f2.x + f3.x);
    float ry = (f0.y + f1.y) + (f2.y + f3.y);
    g_emis[(size_t)t * (BB * KKT) + (2 * bp) * KKT + k]     = rx;
    g_emis[(size_t)t * (BB * KKT) + (2 * bp + 1) * KKT + k] = ry;
}

// ---------------- K5: merged Viterbi + CRF (128 CTAs run concurrently) ----------------
__global__ void vitcrf_kernel(const int* __restrict__ tags,
                              const float* __restrict__ start_t, const float* __restrict__ end_t,
                              const float* __restrict__ trans, float* __restrict__ out)
{
    const int b = blockIdx.x & 63;
    const int k = threadIdx.x;
    __shared__ float sc[KKT], ns[KKT], tr[KKT * KKT];
    __shared__ int hist_s[(TT - 1) * KKT];
    for (int i = k; i < KKT * KKT; i += 32) tr[i] = trans[i];
    __syncwarp();

    if (blockIdx.x < BB) {
        if (k < KKT) sc[k] = start_t[k] + g_emis[(size_t)b * KKT + k];
        float enext = (k < KKT) ? __ldcg(&g_emis[(size_t)(BB + b) * KKT + k]) : 0.f;
        __syncwarp();
        for (int t = 1; t < TT; t++) {
            float ecur = enext;
            if (k < KKT && t + 1 < TT)
                enext = __ldcg(&g_emis[((size_t)(t + 1) * BB + b) * KKT + k]);
            if (k < KKT) {
                float best = -1e30f; int arg = 0;
#pragma unroll
                for (int kp = 0; kp < KKT; kp++) {
                    float v = sc[kp] + tr[kp * KKT + k];
                    if (v > best) { best = v; arg = kp; }
                }
                ns[k] = best + ecur;
                hist_s[(t - 1) * KKT + k] = arg;
            }
            __syncwarp();
            if (k < KKT) sc[k] = ns[k];
            __syncwarp();
        }
        if (k == 0) {
            float best = -1e30f; int last = 0;
#pragma unroll
            for (int kk = 0; kk < KKT; kk++) {
                float v = sc[kk] + end_t[kk];
                if (v > best) { best = v; last = kk; }
            }
            out[(size_t)b * TT + (TT - 1)] = (float)last;
            int tag = last;
            for (int t = TT - 2; t >= 0; t--) {
                tag = hist_s[t * KKT + tag];
                out[(size_t)b * TT + t] = (float)tag;
            }
        }
    } else {
        float partn = 0.f;
        for (int t = k; t < TT; t += 32) {
            int ttg = tags[(size_t)b * TT + t];
            if (t == 0) {
                partn += start_t[ttg] + g_emis[(size_t)b * KKT + ttg];
            } else {
                int tp = tags[(size_t)b * TT + t - 1];
                partn += tr[tp * KKT + ttg] + g_emis[((size_t)t * BB + b) * KKT + ttg];
            }
            if (t == TT - 1) partn += end_t[ttg];
        }
#pragma unroll
        for (int off = 16; off; off >>= 1)
            partn += __shfl_xor_sync(0xffffffffu, partn, off);
        float num = partn;

        if (k < KKT) sc[k] = start_t[k] + g_emis[(size_t)b * KKT + k];
        float enext = (k < KKT) ? __ldcg(&g_emis[(size_t)(BB + b) * KKT + k]) : 0.f;
        __syncwarp();
        for (int t = 1; t < TT; t++) {
            float ecur = enext;
            if (k < KKT && t + 1 < TT)
                enext = __ldcg(&g_emis[((size_t)(t + 1) * BB + b) * KKT + k]);
            if (k < KKT) {
                float mx = -1e30f;
#pragma unroll
                for (int kp = 0; kp < KKT; kp++) mx = fmaxf(mx, sc[kp] + tr[kp * KKT + k]);
                float ssum = 0.f;
#pragma unroll
                for (int kp = 0; kp < KKT; kp++) ssum += expf(sc[kp] + tr[kp * KKT + k] - mx);
                ns[k] = mx + logf(ssum) + ecur;
            }
            __syncwarp();
            if (k < KKT) sc[k] = ns[k];
            __syncwarp();
        }
        if (k == 0) {
            float mx = -1e30f;
#pragma unroll
            for (int kk = 0; kk < KKT; kk++) mx = fmaxf(mx, sc[kk] + end_t[kk]);
            float ssum = 0.f;
#pragma unroll
            for (int kk = 0; kk < KKT; kk++) ssum += expf(sc[kk] + end_t[kk] - mx);
            g_lossb[b] = (mx + logf(ssum)) - num;
        }
    }
}

// ---------------- K6: deterministic loss reduction ----------------
__global__ void finalize_kernel(float* __restrict__ out)
{
    if (blockIdx.x == 0 && threadIdx.x == 0) {
        float s = 0.f;
        for (int b = 0; b < BB; b++) s += g_lossb[b];
        out[(size_t)BB * TT] = s;
    }
}

// ---------------- launch ----------------
extern "C" void kernel_launch(void* const* d_in, const int* in_sizes, int n_in,
                              void* d_out, int out_size)
{
    const int*   tokens  = (const int*)  d_in[0];
    const int*   tags    = (const int*)  d_in[1];
    // d_in[2] = mask (all ones by construction; unused)
    const float* emb     = (const float*)d_in[3];
    const float* w_ih_f  = (const float*)d_in[4];
    const float* w_hh_f  = (const float*)d_in[5];
    const float* b_ih_f  = (const float*)d_in[6];
    const float* b_hh_f  = (const float*)d_in[7];
    const float* w_ih_b  = (const float*)d_in[8];
    const float* w_hh_b  = (const float*)d_in[9];
    const float* b_ih_b  = (const float*)d_in[10];
    const float* b_hh_b  = (const float*)d_in[11];
    const float* h0      = (const float*)d_in[12];
    const float* c0      = (const float*)d_in[13];
    const float* w_out   = (const float*)d_in[14];
    const float* b_out   = (const float*)d_in[15];
    const float* start_t = (const float*)d_in[16];
    const float* end_t   = (const float*)d_in[17];
    const float* trans   = (const float*)d_in[18];
    float* out = (float*)d_out;

    const int rec_smem    = (304 * HROW + 256 * PROW) * 4;   // 152320 bytes
    const int gather_smem = 64 * 305 * 4;                    // 78080 bytes
    const int proj_smem   = KKT * 2 * HH * 8 + PJC * 64 * 4; // 62400 bytes
    static int smem_set = 0;
    if (!smem_set) {
        cudaFuncSetAttribute(lstm_rec_kernel, cudaFuncAttributeMaxDynamicSharedMemorySize, rec_smem);
        cudaFuncSetAttribute(gather_kernel, cudaFuncAttributeMaxDynamicSharedMemorySize, gather_smem);
        cudaFuncSetAttribute(proj_kernel, cudaFuncAttributeMaxDynamicSharedMemorySize, proj_smem);
        smem_set = 1;
    }

    prep_kernel<<<150, 256>>>(b_ih_f, b_hh_f, b_ih_b, b_hh_b, h0);
    gather_kernel<<<TT, 256, gather_smem>>>(tokens, emb);
    gemm_pre_kernel<<<dim3(NCOL / 128, 19), 256>>>(w_ih_f, w_ih_b);
    lstm_rec_kernel<<<2 * NSL, 512, rec_smem>>>(w_hh_f, w_hh_b, c0);
    proj_kernel<<<TT, 288, proj_smem>>>(w_out, b_out);
    vitcrf_kernel<<<2 * BB, 32>>>(tags, start_t, end_t, trans, out);
    finalize_kernel<<<1, 1>>>(out);
}